// round 4
// baseline (speedup 1.0000x reference)
#include <cuda_runtime.h>
#include <math.h>

// ---------------- problem dims ----------------
#define R_   2
#define K_   3
#define N_   16384
#define V_   256
#define E_   1
#define L_   8
#define VE_  128
#define LK_  1
#define OUT_ 64
#define IN_  256
#define HID_ 512
#define C_   5
#define CH_  (C_*HID_)   // 2560

// ---------------- workspace (device globals; no runtime alloc) ----------------
__device__ float g_x1[(size_t)N_ * CH_];          // per-r activations stage 1
__device__ float g_x2[(size_t)N_ * CH_];          // per-r activations stage 2
__device__ float g_outr[(size_t)R_ * N_ * HID_];  // per-relation pooled output
__device__ float g_hfin[(size_t)N_ * HID_];       // globally pooled
__device__ float g_xp[(size_t)R_ * N_ * VE_];     // pooled extra raw feats
__device__ float g_stats1[N_ * 2];                // LN1 mean/rstd per row
__device__ float g_stats2[N_ * 2];                // LN2 mean/rstd per row
__device__ float g_u[R_ * VE_];                   // extra_emb @ w_extra
__device__ float g_Wraw[(size_t)R_ * K_ * V_ * HID_];   // femb @ W1[c], c<3
__device__ float g_Wex [(size_t)R_ * VE_ * HID_];       // extra_emb @ W1[3]
__device__ float g_Wlab[(size_t)R_ * OUT_ * HID_];      // label_emb @ W1[4]

// ---------------- generic tiled fp32 GEMM core ----------------
// C[M,Ncols] = op_A(A[M,Kd]) @ B[Kd,Ncols] (+bias) (opt. PReLU on output)
// op_A (LN_A): a' = prelu((a - mean[row])*rstd[row]*gamma[k] + beta[k], alpha)
constexpr int BN = 128, BK = 16, TN = 8;

template<int BM, int TM, bool LN_A, bool PRELU_OUT>
__device__ __forceinline__ void gemm_core(
    const float* __restrict__ A, int lda, int M, int Kd,
    const float* __restrict__ B, int ldb,
    const float* __restrict__ bias,
    float* __restrict__ Co, int ldc, int Ncols,
    const float* __restrict__ stats,
    const float* __restrict__ gamma,
    const float* __restrict__ beta,
    const float* __restrict__ alpha_p)
{
    constexpr int TX = BN / TN;            // 16
    constexpr int TY = BM / TM;
    constexpr int THREADS = TX * TY;

    __shared__ float As[BK][BM + 4];
    __shared__ float Bs[BK][BN];

    const int tid  = threadIdx.x;
    const int tx   = tid % TX;
    const int ty   = tid / TX;
    const int row0 = blockIdx.y * BM;
    const int col0 = blockIdx.x * BN;

    float alpha = 0.f;
    if constexpr (LN_A || PRELU_OUT) alpha = __ldg(alpha_p);

    float acc[TM][TN];
    #pragma unroll
    for (int i = 0; i < TM; i++)
        #pragma unroll
        for (int j = 0; j < TN; j++) acc[i][j] = 0.f;

    for (int k0 = 0; k0 < Kd; k0 += BK) {
        // ---- load A tile (float4, transposed into As[k][m]) ----
        for (int v = tid; v < BM * (BK / 4); v += THREADS) {
            int r  = v / (BK / 4);
            int kq = (v % (BK / 4)) * 4;
            int gr = row0 + r;
            float4 val = make_float4(0.f, 0.f, 0.f, 0.f);
            if (gr < M) {
                val = *reinterpret_cast<const float4*>(A + (size_t)gr * lda + k0 + kq);
                if constexpr (LN_A) {
                    float mn = stats[2 * gr], rs = stats[2 * gr + 1];
                    float4 gm = *reinterpret_cast<const float4*>(gamma + k0 + kq);
                    float4 bt = *reinterpret_cast<const float4*>(beta  + k0 + kq);
                    val.x = (val.x - mn) * rs * gm.x + bt.x;
                    val.y = (val.y - mn) * rs * gm.y + bt.y;
                    val.z = (val.z - mn) * rs * gm.z + bt.z;
                    val.w = (val.w - mn) * rs * gm.w + bt.w;
                    val.x = val.x >= 0.f ? val.x : alpha * val.x;
                    val.y = val.y >= 0.f ? val.y : alpha * val.y;
                    val.z = val.z >= 0.f ? val.z : alpha * val.z;
                    val.w = val.w >= 0.f ? val.w : alpha * val.w;
                }
            }
            As[kq + 0][r] = val.x;
            As[kq + 1][r] = val.y;
            As[kq + 2][r] = val.z;
            As[kq + 3][r] = val.w;
        }
        // ---- load B tile ----
        for (int v = tid; v < BK * (BN / 4); v += THREADS) {
            int r  = v / (BN / 4);
            int c4 = (v % (BN / 4)) * 4;
            int gc = col0 + c4;
            float4 val = make_float4(0.f, 0.f, 0.f, 0.f);
            if (gc < Ncols)
                val = *reinterpret_cast<const float4*>(B + (size_t)(k0 + r) * ldb + gc);
            *reinterpret_cast<float4*>(&Bs[r][c4]) = val;
        }
        __syncthreads();

        // ---- compute ----
        #pragma unroll
        for (int kk = 0; kk < BK; kk++) {
            float a[TM], b[TN];
            #pragma unroll
            for (int i = 0; i < TM; i += 4) {
                float4 t = *reinterpret_cast<const float4*>(&As[kk][ty * TM + i]);
                a[i] = t.x; a[i + 1] = t.y; a[i + 2] = t.z; a[i + 3] = t.w;
            }
            #pragma unroll
            for (int j = 0; j < TN; j += 4) {
                float4 t = *reinterpret_cast<const float4*>(&Bs[kk][tx * TN + j]);
                b[j] = t.x; b[j + 1] = t.y; b[j + 2] = t.z; b[j + 3] = t.w;
            }
            #pragma unroll
            for (int i = 0; i < TM; i++)
                #pragma unroll
                for (int j = 0; j < TN; j++)
                    acc[i][j] += a[i] * b[j];
        }
        __syncthreads();
    }

    // ---- epilogue ----
    #pragma unroll
    for (int i = 0; i < TM; i++) {
        int gr = row0 + ty * TM + i;
        if (gr >= M) continue;
        float* crow = Co + (size_t)gr * ldc;
        #pragma unroll
        for (int j = 0; j < TN; j++) {
            int gc = col0 + tx * TN + j;
            if (gc < Ncols) {
                float vv = acc[i][j];
                if (bias) vv += bias[gc];
                if constexpr (PRELU_OUT) vv = vv >= 0.f ? vv : alpha * vv;
                crow[gc] = vv;
            }
        }
    }
}

template<int BM, int TM, bool LN_A, bool PRELU_OUT>
__global__ void __launch_bounds__(256, 2) gemm_kernel(
    const float* __restrict__ A, int lda, long long aZ, int M, int Kd,
    const float* __restrict__ B, int ldb, long long bZ,
    const float* __restrict__ bias, long long biasZ,
    float* __restrict__ Co, int ldc, long long cZ, int Ncols,
    const float* __restrict__ stats,
    const float* __restrict__ gamma, const float* __restrict__ beta, long long gZ,
    const float* __restrict__ alpha_p)
{
    long long z = blockIdx.z;
    gemm_core<BM, TM, LN_A, PRELU_OUT>(
        A + z * aZ, lda, M, Kd,
        B + z * bZ, ldb,
        bias ? bias + z * biasZ : nullptr,
        Co + z * cZ, ldc, Ncols,
        stats,
        gamma ? gamma + z * gZ : nullptr,
        beta  ? beta  + z * gZ : nullptr,
        alpha_p);
}

// ---------------- fused-weight precompute: emb @ W1[c] (10 small GEMMs) ----------------
__global__ void __launch_bounds__(256, 2) fuse_weights_kernel(
    const float* __restrict__ femb, const float* __restrict__ eemb,
    const float* __restrict__ lemb, const float* __restrict__ W1)
{
    int z = blockIdx.z;            // 0..9 -> (r, c)
    int r = z / C_, c = z % C_;
    const float* Ap; int M; float* out;
    if (c < K_) {
        Ap = femb + (size_t)(r * K_ + c) * V_ * IN_;  M = V_;
        out = g_Wraw + (size_t)(r * K_ + c) * V_ * HID_;
    } else if (c == 3) {
        Ap = eemb + (size_t)r * VE_ * IN_;            M = VE_;
        out = g_Wex + (size_t)r * VE_ * HID_;
    } else {
        Ap = lemb + (size_t)r * OUT_ * IN_;           M = OUT_;
        out = g_Wlab + (size_t)r * OUT_ * HID_;
    }
    const float* Bp = W1 + (size_t)c * IN_ * HID_;
    gemm_core<64, 4, false, false>(Ap, IN_, M, IN_, Bp, HID_, nullptr,
                                   out, HID_, HID_, nullptr, nullptr, nullptr, nullptr);
}

// ---------------- u[r][v] = extra_emb[r,0,v,:] . w_extra[0,:] ----------------
__global__ void k_u(const float* __restrict__ eemb, const float* __restrict__ w_extra)
{
    int t = blockIdx.x * blockDim.x + threadIdx.x;
    if (t >= R_ * VE_) return;
    int r = t / VE_, v = t % VE_;
    const float* row = eemb + ((size_t)r * VE_ + v) * IN_;
    float s = 0.f;
    for (int d = 0; d < IN_; d++) s += row[d] * w_extra[d];
    g_u[t] = s;
}

// ---------------- extra-feature attention pool in raw space (warp per (r,n)) ----------------
__global__ void __launch_bounds__(256) k_extra_pool(const float* __restrict__ extra)
{
    int wg   = (blockIdx.x * blockDim.x + threadIdx.x) >> 5;
    int lane = threadIdx.x & 31;
    if (wg >= R_ * N_) return;
    int r = wg / N_, n = wg % N_;
    const float* base = extra + (size_t)(r * N_ + n) * (L_ * VE_);

    float u[4];
    #pragma unroll
    for (int j = 0; j < 4; j++) u[j] = g_u[r * VE_ + lane + 32 * j];

    float x[L_][4];
    float s[L_];
    #pragma unroll
    for (int l = 0; l < L_; l++) {
        float p = 0.f;
        #pragma unroll
        for (int j = 0; j < 4; j++) {
            x[l][j] = base[l * VE_ + lane + 32 * j];
            p += x[l][j] * u[j];
        }
        #pragma unroll
        for (int o = 16; o > 0; o >>= 1) p += __shfl_xor_sync(0xffffffffu, p, o);
        s[l] = 1.f / (1.f + expf(-p));           // sigmoid
    }
    float mx = s[0];
    #pragma unroll
    for (int l = 1; l < L_; l++) mx = fmaxf(mx, s[l]);
    float e[L_], esum = 0.f;
    #pragma unroll
    for (int l = 0; l < L_; l++) { e[l] = expf(s[l] - mx); esum += e[l]; }
    float inv = 1.f / esum;

    float out[4] = {0.f, 0.f, 0.f, 0.f};
    #pragma unroll
    for (int l = 0; l < L_; l++) {
        float w = e[l] * inv;
        #pragma unroll
        for (int j = 0; j < 4; j++) out[j] += w * x[l][j];
    }
    float* op = g_xp + (size_t)(r * N_ + n) * VE_;
    #pragma unroll
    for (int j = 0; j < 4; j++) op[lane + 32 * j] = out[j];
}

// ---------------- LayerNorm stats over [C,HID] per row (warp per row) ----------------
__global__ void __launch_bounds__(256) k_stats(const float* __restrict__ X, float* __restrict__ stats)
{
    int w    = (blockIdx.x * blockDim.x + threadIdx.x) >> 5;
    int lane = threadIdx.x & 31;
    if (w >= N_) return;
    const float4* row = reinterpret_cast<const float4*>(X + (size_t)w * CH_);
    float s = 0.f, s2 = 0.f;
    for (int v = lane; v < CH_ / 4; v += 32) {
        float4 t = row[v];
        s  += t.x + t.y + t.z + t.w;
        s2 += t.x * t.x + t.y * t.y + t.z * t.z + t.w * t.w;
    }
    #pragma unroll
    for (int o = 16; o > 0; o >>= 1) {
        s  += __shfl_xor_sync(0xffffffffu, s,  o);
        s2 += __shfl_xor_sync(0xffffffffu, s2, o);
    }
    if (lane == 0) {
        float m   = s / (float)CH_;
        float var = s2 / (float)CH_ - m * m;
        stats[2 * w]     = m;
        stats[2 * w + 1] = rsqrtf(var + 1e-5f);
    }
}

// ---------------- channel attention pool (block per n): LN2+PReLU, sigmoid-softmax over C ----------------
__global__ void __launch_bounds__(256) k_pool_c(
    const float* __restrict__ g2, const float* __restrict__ be2,
    const float* __restrict__ a2p, const float* __restrict__ wr, int r)
{
    int n = blockIdx.x, tid = threadIdx.x;
    __shared__ float sx[CH_];
    __shared__ float red[C_][8];
    __shared__ float salpha[C_];

    float mn = g_stats2[2 * n], rs = g_stats2[2 * n + 1], a = __ldg(a2p);
    const float* xr = g_x2 + (size_t)n * CH_;
    for (int i = tid; i < CH_; i += 256) {
        float v = (xr[i] - mn) * rs * g2[i] + be2[i];   // g2/be2 are [C,HID] contiguous
        sx[i] = v >= 0.f ? v : a * v;
    }
    __syncthreads();

    float p[C_] = {0.f, 0.f, 0.f, 0.f, 0.f};
    for (int h = tid; h < HID_; h += 256) {
        float w = wr[h];
        #pragma unroll
        for (int c = 0; c < C_; c++) p[c] += sx[c * HID_ + h] * w;
    }
    int lane = tid & 31, wid = tid >> 5;
    #pragma unroll
    for (int c = 0; c < C_; c++) {
        #pragma unroll
        for (int o = 16; o > 0; o >>= 1) p[c] += __shfl_xor_sync(0xffffffffu, p[c], o);
    }
    if (lane == 0) {
        #pragma unroll
        for (int c = 0; c < C_; c++) red[c][wid] = p[c];
    }
    __syncthreads();
    if (tid == 0) {
        float s[C_];
        float mx = -1e30f;
        #pragma unroll
        for (int c = 0; c < C_; c++) {
            float t = 0.f;
            #pragma unroll
            for (int w2 = 0; w2 < 8; w2++) t += red[c][w2];
            s[c] = 1.f / (1.f + expf(-t));
            mx = fmaxf(mx, s[c]);
        }
        float esum = 0.f, e[C_];
        #pragma unroll
        for (int c = 0; c < C_; c++) { e[c] = expf(s[c] - mx); esum += e[c]; }
        float inv = 1.f / esum;
        #pragma unroll
        for (int c = 0; c < C_; c++) salpha[c] = e[c] * inv;
    }
    __syncthreads();

    float* op = g_outr + (size_t)r * N_ * HID_ + (size_t)n * HID_;
    for (int h = tid; h < HID_; h += 256) {
        float acc = 0.f;
        #pragma unroll
        for (int c = 0; c < C_; c++) acc += salpha[c] * sx[c * HID_ + h];
        op[h] = acc;
    }
}

// ---------------- global (over R) attention pool (warp per n) ----------------
__global__ void __launch_bounds__(256) k_pool_global(const float* __restrict__ wg)
{
    int w    = (blockIdx.x * blockDim.x + threadIdx.x) >> 5;
    int lane = threadIdx.x & 31;
    if (w >= N_) return;
    const float* pa = g_outr + (size_t)w * HID_;
    const float* pb = g_outr + (size_t)N_ * HID_ + (size_t)w * HID_;
    float a[16], b[16], wv[16];
    float sa = 0.f, sb = 0.f;
    #pragma unroll
    for (int j = 0; j < 16; j++) {
        int h = lane + 32 * j;
        a[j] = pa[h]; b[j] = pb[h]; wv[j] = wg[h];
        sa += a[j] * wv[j]; sb += b[j] * wv[j];
    }
    #pragma unroll
    for (int o = 16; o > 0; o >>= 1) {
        sa += __shfl_xor_sync(0xffffffffu, sa, o);
        sb += __shfl_xor_sync(0xffffffffu, sb, o);
    }
    sa = 1.f / (1.f + expf(-sa));
    sb = 1.f / (1.f + expf(-sb));
    float mx = fmaxf(sa, sb);
    float ea = expf(sa - mx), eb = expf(sb - mx);
    float aa = ea / (ea + eb);
    float ab = 1.f - aa;
    float* op = g_hfin + (size_t)w * HID_;
    #pragma unroll
    for (int j = 0; j < 16; j++) op[lane + 32 * j] = aa * a[j] + ab * b[j];
}

// ---------------- input mapping (resolved from size signature at launch) ----------------
struct Ins {
    const float *raw, *extra, *label, *femb, *eemb, *lemb;
    const float *w_extra, *w_r, *w_g;
    const float *W1, *b1, *g1, *be1, *a1, *W2, *b2, *g2, *be2, *a2;
    const float *Wf1, *bf1, *af, *Wf2, *bf2;
};

static void resolve(void* const* d_in, const int* sz, Ins& I)
{
    auto F = [&](int i) { return (const float*)d_in[i]; };
    if (sz[0] == R_ * K_ * N_ * V_) {
        // dict-insertion order (== reference() parameter order)
        I.raw = F(0);  I.extra = F(1);  I.label = F(2);
        I.femb = F(3); I.eemb = F(4);   I.lemb = F(5);
        I.w_extra = F(6); I.w_r = F(7); I.w_g = F(8);
        I.W1 = F(9);  I.b1 = F(10); I.g1 = F(11); I.be1 = F(12); I.a1 = F(13);
        I.W2 = F(14); I.b2 = F(15); I.g2 = F(16); I.be2 = F(17); I.a2 = F(18);
        I.Wf1 = F(19); I.bf1 = F(20); I.af = F(21); I.Wf2 = F(22); I.bf2 = F(23);
    } else {
        // sorted-key order: W1,W2,Wf1,Wf2,a1,a2,af,b1,b2,be1,be2,bf1,bf2,
        //                   extra_emb,extra_feats,feat_emb,g1,g2,label_emb,
        //                   label_feats,raw_feats,w_extra,w_global,w_r
        I.W1 = F(0);  I.W2 = F(1);  I.Wf1 = F(2); I.Wf2 = F(3);
        I.a1 = F(4);  I.a2 = F(5);  I.af = F(6);
        I.b1 = F(7);  I.b2 = F(8);  I.be1 = F(9); I.be2 = F(10);
        I.bf1 = F(11); I.bf2 = F(12);
        I.eemb = F(13); I.extra = F(14); I.femb = F(15);
        I.g1 = F(16); I.g2 = F(17);
        I.lemb = F(18); I.label = F(19); I.raw = F(20);
        I.w_extra = F(21); I.w_g = F(22); I.w_r = F(23);
    }
}

extern "C" void kernel_launch(void* const* d_in, const int* in_sizes, int n_in,
                              void* d_out, int out_size)
{
    if (n_in < 24) return;
    Ins I;
    resolve(d_in, in_sizes, I);

    float *px1, *px2, *pxp, *pWraw, *pWex, *pWlab, *ps1, *ps2, *phf;
    cudaGetSymbolAddress((void**)&px1,   g_x1);
    cudaGetSymbolAddress((void**)&px2,   g_x2);
    cudaGetSymbolAddress((void**)&pxp,   g_xp);
    cudaGetSymbolAddress((void**)&pWraw, g_Wraw);
    cudaGetSymbolAddress((void**)&pWex,  g_Wex);
    cudaGetSymbolAddress((void**)&pWlab, g_Wlab);
    cudaGetSymbolAddress((void**)&ps1,   g_stats1);
    cudaGetSymbolAddress((void**)&ps2,   g_stats2);
    cudaGetSymbolAddress((void**)&phf,   g_hfin);

    // prolog: u vectors, fused W1 weights, extra pooling (reads extra_feats once)
    k_u<<<1, 256>>>(I.eemb, I.w_extra);
    fuse_weights_kernel<<<dim3(4, 4, 10), 256>>>(I.femb, I.eemb, I.lemb, I.W1);
    k_extra_pool<<<(R_ * N_) / 8, 256>>>(I.extra);

    for (int r = 0; r < R_; r++) {
        // x1: channels 0..2 (raw @ fused weights), batched over z
        gemm_kernel<128, 8, false, false><<<dim3(HID_ / BN, N_ / 128, K_), 256>>>(
            I.raw + (size_t)r * K_ * N_ * V_, V_, (long long)N_ * V_, N_, V_,
            pWraw + (size_t)r * K_ * V_ * HID_, HID_, (long long)V_ * HID_,
            I.b1, HID_,
            px1, CH_, HID_, HID_,
            nullptr, nullptr, nullptr, 0, nullptr);
        // x1: channel 3 (pooled extra @ fused weights)
        gemm_kernel<128, 8, false, false><<<dim3(HID_ / BN, N_ / 128, 1), 256>>>(
            pxp + (size_t)r * N_ * VE_, VE_, 0, N_, VE_,
            pWex + (size_t)r * VE_ * HID_, HID_, 0,
            I.b1 + 3 * HID_, 0,
            px1 + 3 * HID_, CH_, 0, HID_,
            nullptr, nullptr, nullptr, 0, nullptr);
        // x1: channel 4 (label @ fused weights)
        gemm_kernel<128, 8, false, false><<<dim3(HID_ / BN, N_ / 128, 1), 256>>>(
            I.label + (size_t)r * N_ * OUT_, OUT_, 0, N_, OUT_,
            pWlab + (size_t)r * OUT_ * HID_, HID_, 0,
            I.b1 + 4 * HID_, 0,
            px1 + 4 * HID_, CH_, 0, HID_,
            nullptr, nullptr, nullptr, 0, nullptr);

        // LN1 stats; x2 = prelu(LN(x1)) @ W2 + b2  (LN+PReLU fused into A-load), z over channels
        k_stats<<<N_ / 8, 256>>>(px1, ps1);
        gemm_kernel<128, 8, true, false><<<dim3(HID_ / BN, N_ / 128, C_), 256>>>(
            px1, CH_, (long long)HID_, N_, HID_,
            I.W2, HID_, (long long)HID_ * HID_,
            I.b2, HID_,
            px2, CH_, HID_, HID_,
            ps1, I.g1, I.be1, HID_, I.a1);

        // LN2 stats; per-n channel attention pool (LN2+PReLU fused)
        k_stats<<<N_ / 8, 256>>>(px2, ps2);
        k_pool_c<<<N_, 256>>>(I.g2, I.be2, I.a2, I.w_r + r * HID_, r);
    }

    // pool over relations, then feed-forward head
    k_pool_global<<<N_ / 8, 256>>>(I.w_g);
    gemm_kernel<128, 8, false, true><<<dim3(HID_ / BN, N_ / 128, 1), 256>>>(
        phf, HID_, 0, N_, HID_,
        I.Wf1, HID_, 0,
        I.bf1, 0,
        px1, HID_, 0, HID_,             // reuse g_x1 as z buffer
        nullptr, nullptr, nullptr, 0, I.af);
    gemm_kernel<128, 8, false, false><<<dim3(1, N_ / 128, 1), 256>>>(
        px1, HID_, 0, N_, HID_,
        I.Wf2, OUT_, 0,
        I.bf2, 0,
        (float*)d_out, OUT_, 0, OUT_,
        nullptr, nullptr, nullptr, 0, nullptr);
}